// round 2
// baseline (speedup 1.0000x reference)
#include <cuda_runtime.h>
#include <cuda_bf16.h>
#include <cstdint>

// ---------------------------------------------------------------------------
// out[t,o] = sum_i (x[t,i]*scales[i]) * W[o,i]
//   x [32,4096] f32, W [14336,4096] int32 (int8-valued), scales [4096] f32
//   out [32,14336] f32
//
// HMMA (mma.sync m16n8k16 bf16) version — tcgen05 PTX is rejected because the
// harness compiles at compute_103 (no 'a' feature target).
// D[o(128), t(32)] per CTA; xs split into bf16 hi+lo, both accumulated into
// the same fp32 accumulators => fp32-level accuracy.
// ---------------------------------------------------------------------------

#define SWZ(off) ((off) ^ (((off) >> 3) & 0x70))

static constexpr int TOKENS = 32;
static constexpr int INF    = 4096;
static constexpr int OUTF   = 14336;
static constexpr int TILE_M = 128;
static constexpr int KC     = 64;          // bf16 K elements per chunk
static constexpr int NITER  = INF / KC;    // 64

// static SMEM layout (bytes)
static constexpr int A_OFF   = 0;                 // W tile 128x64 bf16, 128B rows, SW128
static constexpr int A_BYTES = TILE_M * 128;      // 16384
static constexpr int BH_OFF  = A_OFF + A_BYTES;   // xs_hi tile 32x64 bf16
static constexpr int B_BYTES = 32 * 128;          // 4096
static constexpr int BL_OFF  = BH_OFF + B_BYTES;  // xs_lo tile
static constexpr int SMEM_TOTAL = BL_OFF + B_BYTES;  // 24576

// split-bf16 scaled activations (built by prep kernel)
__device__ __nv_bfloat16 g_xs_hi[TOKENS * INF];
__device__ __nv_bfloat16 g_xs_lo[TOKENS * INF];

// ---------------- helpers ----------------
__device__ __forceinline__ uint32_t smem_u32(const void* p) {
    uint32_t a;
    asm("{ .reg .u64 t; cvta.to.shared.u64 t, %1; cvt.u32.u64 %0, t; }"
        : "=r"(a) : "l"(p));
    return a;
}

__device__ __forceinline__ void sts128(uint32_t addr, uint32_t r0, uint32_t r1,
                                       uint32_t r2, uint32_t r3) {
    asm volatile("st.shared.v4.b32 [%0], {%1, %2, %3, %4};"
                 :: "r"(addr), "r"(r0), "r"(r1), "r"(r2), "r"(r3) : "memory");
}

// pack ints (int8-range, exact in bf16) -> bf16x2 {lo half = a, hi half = b}
__device__ __forceinline__ uint32_t packbf(int a, int b) {
    float fa = (float)a, fb = (float)b;
    uint32_t r;
    asm("cvt.rn.bf16x2.f32 %0, %1, %2;" : "=r"(r) : "f"(fb), "f"(fa));
    return r;
}

__device__ __forceinline__ void ldsm_x4(uint32_t addr, uint32_t& r0, uint32_t& r1,
                                        uint32_t& r2, uint32_t& r3) {
    asm volatile("ldmatrix.sync.aligned.m8n8.x4.shared.b16 {%0,%1,%2,%3}, [%4];"
                 : "=r"(r0), "=r"(r1), "=r"(r2), "=r"(r3) : "r"(addr));
}

__device__ __forceinline__ void mma_16816(float* d, const uint32_t* a, const uint32_t* b) {
    asm volatile(
        "mma.sync.aligned.m16n8k16.row.col.f32.bf16.bf16.f32 "
        "{%0,%1,%2,%3}, {%4,%5,%6,%7}, {%8,%9}, {%0,%1,%2,%3};"
        : "+f"(d[0]), "+f"(d[1]), "+f"(d[2]), "+f"(d[3])
        : "r"(a[0]), "r"(a[1]), "r"(a[2]), "r"(a[3]), "r"(b[0]), "r"(b[1]));
}

// ---------------- prep: xs = x*scales split into bf16 hi/lo ----------------
__global__ void prep_kernel(const float* __restrict__ x, const float* __restrict__ s) {
    int i = blockIdx.x * blockDim.x + threadIdx.x;
    if (i < TOKENS * INF) {
        int k = i & (INF - 1);
        float v = x[i] * s[k];
        __nv_bfloat16 h = __float2bfloat16(v);
        g_xs_hi[i] = h;
        g_xs_lo[i] = __float2bfloat16(v - __bfloat162float(h));
    }
}

// ---------------- main GEMM ----------------
__global__ void __launch_bounds__(256, 1)
qgemm_kernel(const int* __restrict__ W, float* __restrict__ out) {
    __shared__ __align__(1024) char smem[SMEM_TOTAL];
    const uint32_t sb = smem_u32(smem);
    const int tid = threadIdx.x;
    const int wid = tid >> 5;
    const int lane = tid & 31;
    const int row_base = blockIdx.x * TILE_M;

    // ---- per-thread STS coordinates (4 weight granules of 8 ints) ----
    int wm[4], wg[4];
#pragma unroll
    for (int p = 0; p < 4; p++) {
        int gi = tid + p * 256;
        wm[p] = gi >> 3;     // 0..127 row
        wg[p] = gi & 7;      // 0..7 granule -> 16B col offset
    }
    // xs granules: idx = tid + q*256 -> {arr(hi/lo), token, granule}
    int xt[2], xg[2], xarr[2];
#pragma unroll
    for (int q = 0; q < 2; q++) {
        int idx = tid + q * 256;
        xarr[q] = idx >> 8;
        int rem = idx & 255;
        xt[q] = rem >> 3;
        xg[q] = rem & 7;
    }

    // ---- ldmatrix lane geometry ----
    // A frag (warp's 16 rows x 16 k): tiles {r0-7/k0-7, r8-15/k0-7, r0-7/k8-15, r8-15/k8-15}
    const int rowA  = wid * 16 + (lane & 7) + (lane & 8);
    const int aCsel = (lane & 16);        // +8 bf16 cols -> +16 bytes
    // B frag (8 tokens x 16 k, two n-groups per x4):
    // tiles {t0-7/k0-7, t0-7/k8-15, t8-15/k0-7, t8-15/k8-15}
    const int tokB  = (lane & 7) + ((lane & 16) >> 1);
    const int bCsel = (lane & 8) * 2;     // +16 bytes for k+8 tile

    const uint32_t sa  = sb + A_OFF;
    const uint32_t sbh = sb + BH_OFF;
    const uint32_t sbl = sb + BL_OFF;

    float acc[4][4];
#pragma unroll
    for (int n = 0; n < 4; n++)
#pragma unroll
        for (int r = 0; r < 4; r++) acc[n][r] = 0.0f;

    int4 wreg[8];
    uint4 xreg[2];

    // prefetch chunk 0
#pragma unroll
    for (int p = 0; p < 4; p++) {
        const int4* ptr = (const int4*)(W + (size_t)(row_base + wm[p]) * INF + wg[p] * 8);
        wreg[2 * p]     = ptr[0];
        wreg[2 * p + 1] = ptr[1];
    }
#pragma unroll
    for (int q = 0; q < 2; q++) {
        const __nv_bfloat16* src = xarr[q] ? g_xs_lo : g_xs_hi;
        xreg[q] = *(const uint4*)(src + xt[q] * INF + xg[q] * 8);
    }

#pragma unroll 1
    for (int it = 0; it < NITER; ++it) {
        __syncthreads();   // previous chunk's consumers are done with SMEM

        // ---- convert + store W tile (SW128) ----
#pragma unroll
        for (int p = 0; p < 4; p++) {
            int4 a0 = wreg[2 * p], a1 = wreg[2 * p + 1];
            uint32_t r0 = packbf(a0.x, a0.y);
            uint32_t r1 = packbf(a0.z, a0.w);
            uint32_t r2 = packbf(a1.x, a1.y);
            uint32_t r3 = packbf(a1.z, a1.w);
            sts128(sa + SWZ(wm[p] * 128 + wg[p] * 16), r0, r1, r2, r3);
        }
        // ---- store xs tiles ----
#pragma unroll
        for (int q = 0; q < 2; q++) {
            uint32_t base = xarr[q] ? sbl : sbh;
            sts128(base + SWZ(xt[q] * 128 + xg[q] * 16),
                   xreg[q].x, xreg[q].y, xreg[q].z, xreg[q].w);
        }

        // ---- prefetch next chunk (latency overlaps barrier + MMA phase) ----
        if (it + 1 < NITER) {
            const int k0 = (it + 1) * KC;
#pragma unroll
            for (int p = 0; p < 4; p++) {
                const int4* ptr =
                    (const int4*)(W + (size_t)(row_base + wm[p]) * INF + k0 + wg[p] * 8);
                wreg[2 * p]     = ptr[0];
                wreg[2 * p + 1] = ptr[1];
            }
#pragma unroll
            for (int q = 0; q < 2; q++) {
                const __nv_bfloat16* src = xarr[q] ? g_xs_lo : g_xs_hi;
                xreg[q] = *(const uint4*)(src + xt[q] * INF + k0 + xg[q] * 8);
            }
        }

        __syncthreads();   // tile visible

        // ---- compute: 4 k16-steps, 4 n-tiles, hi+lo into same fp32 acc ----
#pragma unroll
        for (int ks = 0; ks < 4; ks++) {
            uint32_t a[4], b[8];
            const int kb = ks * 32;

            ldsm_x4(sa + SWZ(rowA * 128 + kb + aCsel), a[0], a[1], a[2], a[3]);

            const int bb0 = tokB * 128 + kb + bCsel;
            const int bb1 = (tokB + 16) * 128 + kb + bCsel;

            // hi split
            ldsm_x4(sbh + SWZ(bb0), b[0], b[1], b[2], b[3]);
            ldsm_x4(sbh + SWZ(bb1), b[4], b[5], b[6], b[7]);
            mma_16816(acc[0], a, b + 0);
            mma_16816(acc[1], a, b + 2);
            mma_16816(acc[2], a, b + 4);
            mma_16816(acc[3], a, b + 6);
            // lo split
            ldsm_x4(sbl + SWZ(bb0), b[0], b[1], b[2], b[3]);
            ldsm_x4(sbl + SWZ(bb1), b[4], b[5], b[6], b[7]);
            mma_16816(acc[0], a, b + 0);
            mma_16816(acc[1], a, b + 2);
            mma_16816(acc[2], a, b + 4);
            mma_16816(acc[3], a, b + 6);
        }
    }

    // ---- epilogue: d-frag (g,2t),(g,2t+1),(g+8,2t),(g+8,2t+1) ----
    const int g = lane >> 2;
    const int t2 = (lane & 3) * 2;
    const int f0 = row_base + wid * 16 + g;
#pragma unroll
    for (int nt = 0; nt < 4; nt++) {
        const int tok = nt * 8 + t2;
        out[(size_t)tok * OUTF + f0]           = acc[nt][0];
        out[(size_t)(tok + 1) * OUTF + f0]     = acc[nt][1];
        out[(size_t)tok * OUTF + f0 + 8]       = acc[nt][2];
        out[(size_t)(tok + 1) * OUTF + f0 + 8] = acc[nt][3];
    }
}

// ---------------- launch ----------------
extern "C" void kernel_launch(void* const* d_in, const int* in_sizes, int n_in,
                              void* d_out, int out_size) {
    const float* x      = (const float*)d_in[0];
    const int*   weight = (const int*)d_in[1];
    const float* scales = (const float*)d_in[2];
    float*       out    = (float*)d_out;
    (void)in_sizes; (void)n_in; (void)out_size;

    prep_kernel<<<(TOKENS * INF + 255) / 256, 256>>>(x, scales);
    qgemm_kernel<<<OUTF / TILE_M, 256>>>(weight, out);
}

// round 3
// speedup vs baseline: 1.1748x; 1.1748x over previous
#include <cuda_runtime.h>
#include <cuda_bf16.h>
#include <cstdint>

// ---------------------------------------------------------------------------
// out[t,o] = sum_i (x[t,i]*scales[i]) * W[o,i]
//   x [32,4096] f32, W [14336,4096] int32 (int8-valued), scales [4096] f32
//   out [32,14336] f32
//
// HMMA m16n8k16 bf16, xs split into bf16 hi+lo accumulated in fp32.
// R3: TILE_M=64 (grid 224, 2 CTAs/SM) + double-buffered SMEM with a single
// __syncthreads per K-chunk — attack the latency/occupancy bound seen in R2.
// ---------------------------------------------------------------------------

#define SWZ(off) ((off) ^ (((off) >> 3) & 0x70))

static constexpr int TOKENS = 32;
static constexpr int INF    = 4096;
static constexpr int OUTF   = 14336;
static constexpr int TILE_M = 64;
static constexpr int KC     = 64;          // bf16 K elements per chunk
static constexpr int NITER  = INF / KC;    // 64

// per-buffer SMEM layout (bytes)
static constexpr int A_BYTES = TILE_M * 128;        // 8192 (64 rows x 128B, SW128)
static constexpr int B_BYTES = TOKENS * 128;        // 4096
static constexpr int BH_OFF  = A_BYTES;             // xs_hi
static constexpr int BL_OFF  = A_BYTES + B_BYTES;   // xs_lo
static constexpr int BUF_BYTES  = A_BYTES + 2 * B_BYTES;  // 16384
static constexpr int SMEM_TOTAL = 2 * BUF_BYTES;          // 32768

// split-bf16 scaled activations (built by prep kernel)
__device__ __nv_bfloat16 g_xs_hi[TOKENS * INF];
__device__ __nv_bfloat16 g_xs_lo[TOKENS * INF];

// ---------------- helpers ----------------
__device__ __forceinline__ uint32_t smem_u32(const void* p) {
    uint32_t a;
    asm("{ .reg .u64 t; cvta.to.shared.u64 t, %1; cvt.u32.u64 %0, t; }"
        : "=r"(a) : "l"(p));
    return a;
}

__device__ __forceinline__ void sts128(uint32_t addr, uint32_t r0, uint32_t r1,
                                       uint32_t r2, uint32_t r3) {
    asm volatile("st.shared.v4.b32 [%0], {%1, %2, %3, %4};"
                 :: "r"(addr), "r"(r0), "r"(r1), "r"(r2), "r"(r3) : "memory");
}

// pack ints (int8-range, exact in bf16) -> bf16x2 {lo half = a, hi half = b}
__device__ __forceinline__ uint32_t packbf(int a, int b) {
    float fa = (float)a, fb = (float)b;
    uint32_t r;
    asm("cvt.rn.bf16x2.f32 %0, %1, %2;" : "=r"(r) : "f"(fb), "f"(fa));
    return r;
}

__device__ __forceinline__ void ldsm_x4(uint32_t addr, uint32_t& r0, uint32_t& r1,
                                        uint32_t& r2, uint32_t& r3) {
    asm volatile("ldmatrix.sync.aligned.m8n8.x4.shared.b16 {%0,%1,%2,%3}, [%4];"
                 : "=r"(r0), "=r"(r1), "=r"(r2), "=r"(r3) : "r"(addr));
}

__device__ __forceinline__ void mma_16816(float* d, const uint32_t* a, const uint32_t* b) {
    asm volatile(
        "mma.sync.aligned.m16n8k16.row.col.f32.bf16.bf16.f32 "
        "{%0,%1,%2,%3}, {%4,%5,%6,%7}, {%8,%9}, {%0,%1,%2,%3};"
        : "+f"(d[0]), "+f"(d[1]), "+f"(d[2]), "+f"(d[3])
        : "r"(a[0]), "r"(a[1]), "r"(a[2]), "r"(a[3]), "r"(b[0]), "r"(b[1]));
}

// ---------------- prep: xs = x*scales split into bf16 hi/lo ----------------
__global__ void prep_kernel(const float* __restrict__ x, const float* __restrict__ s) {
    int i = blockIdx.x * blockDim.x + threadIdx.x;
    if (i < TOKENS * INF) {
        int k = i & (INF - 1);
        float v = x[i] * s[k];
        __nv_bfloat16 h = __float2bfloat16(v);
        g_xs_hi[i] = h;
        g_xs_lo[i] = __float2bfloat16(v - __bfloat162float(h));
    }
}

// ---------------- main GEMM ----------------
__global__ void __launch_bounds__(256, 2)
qgemm_kernel(const int* __restrict__ W, float* __restrict__ out) {
    __shared__ __align__(1024) char smem[SMEM_TOTAL];
    const uint32_t sb = smem_u32(smem);
    const int tid = threadIdx.x;
    const int lane = tid & 31;
    const int wid = tid >> 5;
    const int rg = wid >> 1;     // row group 0..3 (16 rows each)
    const int th = wid & 1;      // token half 0..1 (16 tokens each)
    const int row_base = blockIdx.x * TILE_M;

    // ---- per-thread STS coordinates ----
    // W chunk: 64 rows x 8 granules(16B) = 512 granules, 2 per thread
    int wm[2], wg[2];
#pragma unroll
    for (int p = 0; p < 2; p++) {
        int gi = tid + p * 256;
        wm[p] = gi >> 3;     // 0..63 row
        wg[p] = gi & 7;      // 0..7 granule
    }
    // xs granules: idx = tid + q*256 -> {arr(hi/lo), token, granule}
    int xt[2], xg[2], xarr[2];
#pragma unroll
    for (int q = 0; q < 2; q++) {
        int idx = tid + q * 256;
        xarr[q] = idx >> 8;
        int rem = idx & 255;
        xt[q] = rem >> 3;
        xg[q] = rem & 7;
    }

    // ---- ldmatrix lane geometry ----
    // A: warp's 16 rows x 16 k: tiles {r0-7/k0, r8-15/k0, r0-7/k8, r8-15/k8}
    const int rowA  = rg * 16 + (lane & 7) + (lane & 8);
    const int aCsel = (lane & 16);              // +8 bf16 cols -> +16 bytes
    // B: warp's 16 tokens x 16 k: tiles {t0-7/k0, t0-7/k8, t8-15/k0, t8-15/k8}
    const int tokB  = th * 16 + (lane & 7) + ((lane & 16) >> 1);
    const int bCsel = (lane & 8) * 2;           // +16 bytes for k+8 tile

    float acc[2][4];
#pragma unroll
    for (int n = 0; n < 2; n++)
#pragma unroll
        for (int r = 0; r < 4; r++) acc[n][r] = 0.0f;

    int4 wreg[4];
    uint4 xreg[2];

    // prefetch chunk 0
#pragma unroll
    for (int p = 0; p < 2; p++) {
        const int4* ptr = (const int4*)(W + (size_t)(row_base + wm[p]) * INF + wg[p] * 8);
        wreg[2 * p]     = ptr[0];
        wreg[2 * p + 1] = ptr[1];
    }
#pragma unroll
    for (int q = 0; q < 2; q++) {
        const __nv_bfloat16* src = xarr[q] ? g_xs_lo : g_xs_hi;
        xreg[q] = *(const uint4*)(src + xt[q] * INF + xg[q] * 8);
    }

#pragma unroll 1
    for (int it = 0; it < NITER; ++it) {
        const uint32_t bufb = sb + (it & 1) * BUF_BYTES;

        // ---- convert + store W tile (SW128) ----
#pragma unroll
        for (int p = 0; p < 2; p++) {
            int4 a0 = wreg[2 * p], a1 = wreg[2 * p + 1];
            uint32_t r0 = packbf(a0.x, a0.y);
            uint32_t r1 = packbf(a0.z, a0.w);
            uint32_t r2 = packbf(a1.x, a1.y);
            uint32_t r3 = packbf(a1.z, a1.w);
            sts128(bufb + SWZ(wm[p] * 128 + wg[p] * 16), r0, r1, r2, r3);
        }
        // ---- store xs tiles ----
#pragma unroll
        for (int q = 0; q < 2; q++) {
            uint32_t base = bufb + (xarr[q] ? BL_OFF : BH_OFF);
            sts128(base + SWZ(xt[q] * 128 + xg[q] * 16),
                   xreg[q].x, xreg[q].y, xreg[q].z, xreg[q].w);
        }

        // ---- prefetch next chunk (latency hidden behind barrier + MMA) ----
        if (it + 1 < NITER) {
            const int k0 = (it + 1) * KC;
#pragma unroll
            for (int p = 0; p < 2; p++) {
                const int4* ptr =
                    (const int4*)(W + (size_t)(row_base + wm[p]) * INF + k0 + wg[p] * 8);
                wreg[2 * p]     = ptr[0];
                wreg[2 * p + 1] = ptr[1];
            }
#pragma unroll
            for (int q = 0; q < 2; q++) {
                const __nv_bfloat16* src = xarr[q] ? g_xs_lo : g_xs_hi;
                xreg[q] = *(const uint4*)(src + xt[q] * INF + k0 + xg[q] * 8);
            }
        }

        __syncthreads();   // tile (it) visible; buf[(it+1)&1] free for next STS

        // ---- compute: 4 k16-steps, 2 n-groups, hi+lo into same fp32 acc ----
        const uint32_t sbh = bufb + BH_OFF;
        const uint32_t sbl = bufb + BL_OFF;
#pragma unroll
        for (int ks = 0; ks < 4; ks++) {
            uint32_t a[4], b[4];
            const int kb = ks * 32;

            ldsm_x4(bufb + SWZ(rowA * 128 + kb + aCsel), a[0], a[1], a[2], a[3]);

            const int bb = tokB * 128 + kb + bCsel;
            // hi split
            ldsm_x4(sbh + SWZ(bb), b[0], b[1], b[2], b[3]);
            mma_16816(acc[0], a, b + 0);
            mma_16816(acc[1], a, b + 2);
            // lo split
            ldsm_x4(sbl + SWZ(bb), b[0], b[1], b[2], b[3]);
            mma_16816(acc[0], a, b + 0);
            mma_16816(acc[1], a, b + 2);
        }
    }

    // ---- epilogue: d-frag rows (g, g+8), cols (2t, 2t+1) ----
    const int g = lane >> 2;
    const int t2 = (lane & 3) * 2;
    const int f0 = row_base + rg * 16 + g;
#pragma unroll
    for (int nt = 0; nt < 2; nt++) {
        const int tok = th * 16 + nt * 8 + t2;
        out[(size_t)tok * OUTF + f0]           = acc[nt][0];
        out[(size_t)(tok + 1) * OUTF + f0]     = acc[nt][1];
        out[(size_t)tok * OUTF + f0 + 8]       = acc[nt][2];
        out[(size_t)(tok + 1) * OUTF + f0 + 8] = acc[nt][3];
    }
}

// ---------------- launch ----------------
extern "C" void kernel_launch(void* const* d_in, const int* in_sizes, int n_in,
                              void* d_out, int out_size) {
    const float* x      = (const float*)d_in[0];
    const int*   weight = (const int*)d_in[1];
    const float* scales = (const float*)d_in[2];
    float*       out    = (float*)d_out;
    (void)in_sizes; (void)n_in; (void)out_size;

    prep_kernel<<<(TOKENS * INF + 255) / 256, 256>>>(x, scales);
    qgemm_kernel<<<OUTF / TILE_M, 256>>>(weight, out);
}

// round 4
// speedup vs baseline: 1.4799x; 1.2597x over previous
#include <cuda_runtime.h>
#include <cuda_bf16.h>
#include <cstdint>

// ---------------------------------------------------------------------------
// out[t,o] = sum_i (x[t,i]*scales[i]) * W[o,i]
//   x [32,4096] f32, W [14336,4096] int32 (int8-valued), scales [4096] f32
//   out [32,14336] f32
//
// HMMA m16n8k16 bf16, xs split into bf16 hi+lo accumulated in fp32.
// R4: split-K x2 (448 units, ~3 CTAs/SM via __launch_bounds__(256,3)) +
// cp.async for xs tiles + atomicAdd epilogue over a zeroed output.
// 2 contributors per output element => fp32 add commutes => deterministic.
// ---------------------------------------------------------------------------

#define SWZ(off) ((off) ^ (((off) >> 3) & 0x70))

static constexpr int TOKENS = 32;
static constexpr int INF    = 4096;
static constexpr int OUTF   = 14336;
static constexpr int TILE_M = 64;
static constexpr int KSPLIT = 2;
static constexpr int KHALF  = INF / KSPLIT;     // 2048
static constexpr int KC     = 64;               // bf16 K elements per chunk
static constexpr int NITER  = KHALF / KC;       // 32

// per-buffer SMEM layout (bytes)
static constexpr int A_BYTES = TILE_M * 128;        // 8192 (64 rows x 128B, SW128)
static constexpr int B_BYTES = TOKENS * 128;        // 4096
static constexpr int BH_OFF  = A_BYTES;             // xs_hi
static constexpr int BL_OFF  = A_BYTES + B_BYTES;   // xs_lo
static constexpr int BUF_BYTES  = A_BYTES + 2 * B_BYTES;  // 16384
static constexpr int SMEM_TOTAL = 2 * BUF_BYTES;          // 32768

// split-bf16 scaled activations (built by prep kernel)
__device__ __nv_bfloat16 g_xs_hi[TOKENS * INF];
__device__ __nv_bfloat16 g_xs_lo[TOKENS * INF];

// ---------------- helpers ----------------
__device__ __forceinline__ uint32_t smem_u32(const void* p) {
    uint32_t a;
    asm("{ .reg .u64 t; cvta.to.shared.u64 t, %1; cvt.u32.u64 %0, t; }"
        : "=r"(a) : "l"(p));
    return a;
}

__device__ __forceinline__ void sts128(uint32_t addr, uint32_t r0, uint32_t r1,
                                       uint32_t r2, uint32_t r3) {
    asm volatile("st.shared.v4.b32 [%0], {%1, %2, %3, %4};"
                 :: "r"(addr), "r"(r0), "r"(r1), "r"(r2), "r"(r3) : "memory");
}

__device__ __forceinline__ void cp16(uint32_t dst, const void* src) {
    asm volatile("cp.async.cg.shared.global [%0], [%1], 16;"
                 :: "r"(dst), "l"(src) : "memory");
}
__device__ __forceinline__ void cp_commit() {
    asm volatile("cp.async.commit_group;" ::: "memory");
}
__device__ __forceinline__ void cp_wait0() {
    asm volatile("cp.async.wait_group 0;" ::: "memory");
}

// pack ints (int8-range, exact in bf16) -> bf16x2 {lo half = a, hi half = b}
__device__ __forceinline__ uint32_t packbf(int a, int b) {
    float fa = (float)a, fb = (float)b;
    uint32_t r;
    asm("cvt.rn.bf16x2.f32 %0, %1, %2;" : "=r"(r) : "f"(fb), "f"(fa));
    return r;
}

__device__ __forceinline__ void ldsm_x4(uint32_t addr, uint32_t& r0, uint32_t& r1,
                                        uint32_t& r2, uint32_t& r3) {
    asm volatile("ldmatrix.sync.aligned.m8n8.x4.shared.b16 {%0,%1,%2,%3}, [%4];"
                 : "=r"(r0), "=r"(r1), "=r"(r2), "=r"(r3) : "r"(addr));
}

__device__ __forceinline__ void mma_16816(float* d, const uint32_t* a, const uint32_t* b) {
    asm volatile(
        "mma.sync.aligned.m16n8k16.row.col.f32.bf16.bf16.f32 "
        "{%0,%1,%2,%3}, {%4,%5,%6,%7}, {%8,%9}, {%0,%1,%2,%3};"
        : "+f"(d[0]), "+f"(d[1]), "+f"(d[2]), "+f"(d[3])
        : "r"(a[0]), "r"(a[1]), "r"(a[2]), "r"(a[3]), "r"(b[0]), "r"(b[1]));
}

// ---------------- prep: xs = x*scales split into bf16 hi/lo ----------------
__global__ void prep_kernel(const float* __restrict__ x, const float* __restrict__ s) {
    int i = blockIdx.x * blockDim.x + threadIdx.x;
    if (i < TOKENS * INF) {
        int k = i & (INF - 1);
        float v = x[i] * s[k];
        __nv_bfloat16 h = __float2bfloat16(v);
        g_xs_hi[i] = h;
        g_xs_lo[i] = __float2bfloat16(v - __bfloat162float(h));
    }
}

// ---------------- main GEMM ----------------
__global__ void __launch_bounds__(256, 3)
qgemm_kernel(const int* __restrict__ W, float* __restrict__ out) {
    __shared__ __align__(1024) char smem[SMEM_TOTAL];
    const uint32_t sb = smem_u32(smem);
    const int tid = threadIdx.x;
    const int lane = tid & 31;
    const int wid = tid >> 5;
    const int rg = wid >> 1;     // row group 0..3 (16 rows each)
    const int th = wid & 1;      // token half 0..1 (16 tokens each)

    const int tile = blockIdx.x >> 1;
    const int kbase = (blockIdx.x & 1) * KHALF;
    const int row_base = tile * TILE_M;

    // ---- per-thread STS coordinates ----
    // W chunk: 64 rows x 8 granules(8 weights) = 512 granules, 2 per thread
    int wm[2], wg[2];
#pragma unroll
    for (int p = 0; p < 2; p++) {
        int gi = tid + p * 256;
        wm[p] = gi >> 3;     // 0..63 row
        wg[p] = gi & 7;      // 0..7 granule
    }
    // xs granules: idx = tid + q*256 -> {arr(hi/lo), token, granule}
    int xt[2], xg[2], xarr[2];
#pragma unroll
    for (int q = 0; q < 2; q++) {
        int idx = tid + q * 256;
        xarr[q] = idx >> 8;
        int rem = idx & 255;
        xt[q] = rem >> 3;
        xg[q] = rem & 7;
    }

    // ---- ldmatrix lane geometry ----
    const int rowA  = rg * 16 + (lane & 7) + (lane & 8);
    const int aCsel = (lane & 16);              // +8 bf16 cols -> +16 bytes
    const int tokB  = th * 16 + (lane & 7) + ((lane & 16) >> 1);
    const int bCsel = (lane & 8) * 2;           // +16 bytes for k+8 tile

    float acc[2][4];
#pragma unroll
    for (int n = 0; n < 2; n++)
#pragma unroll
        for (int r = 0; r < 4; r++) acc[n][r] = 0.0f;

    int4 wreg[4];

    // ---- prologue: W regs + xs cp.async for chunk 0 ----
#pragma unroll
    for (int p = 0; p < 2; p++) {
        const int4* ptr =
            (const int4*)(W + (size_t)(row_base + wm[p]) * INF + kbase + wg[p] * 8);
        wreg[2 * p]     = ptr[0];
        wreg[2 * p + 1] = ptr[1];
    }
#pragma unroll
    for (int q = 0; q < 2; q++) {
        const __nv_bfloat16* src = xarr[q] ? g_xs_lo : g_xs_hi;
        cp16(sb + (xarr[q] ? BL_OFF : BH_OFF) + SWZ(xt[q] * 128 + xg[q] * 16),
             src + xt[q] * INF + kbase + xg[q] * 8);
    }
    cp_commit();

#pragma unroll 1
    for (int it = 0; it < NITER; ++it) {
        const uint32_t bufb = sb + (it & 1) * BUF_BYTES;

        // ---- convert + store W tile (SW128); buf readers done via sync(it-1) ----
#pragma unroll
        for (int p = 0; p < 2; p++) {
            int4 a0 = wreg[2 * p], a1 = wreg[2 * p + 1];
            uint32_t r0 = packbf(a0.x, a0.y);
            uint32_t r1 = packbf(a0.z, a0.w);
            uint32_t r2 = packbf(a1.x, a1.y);
            uint32_t r3 = packbf(a1.z, a1.w);
            sts128(bufb + SWZ(wm[p] * 128 + wg[p] * 16), r0, r1, r2, r3);
        }

        // ---- prefetch next W chunk into regs ----
        if (it + 1 < NITER) {
            const int k0 = kbase + (it + 1) * KC;
#pragma unroll
            for (int p = 0; p < 2; p++) {
                const int4* ptr =
                    (const int4*)(W + (size_t)(row_base + wm[p]) * INF + k0 + wg[p] * 8);
                wreg[2 * p]     = ptr[0];
                wreg[2 * p + 1] = ptr[1];
            }
        }

        cp_wait0();        // xs(it) landed
        __syncthreads();   // tile (it) visible; compute(it-1) done on all warps

        // ---- xs(it+1) cp.async into the other buffer (readers proven done) ----
        if (it + 1 < NITER) {
            const uint32_t nb = sb + ((it + 1) & 1) * BUF_BYTES;
            const int k0 = kbase + (it + 1) * KC;
#pragma unroll
            for (int q = 0; q < 2; q++) {
                const __nv_bfloat16* src = xarr[q] ? g_xs_lo : g_xs_hi;
                cp16(nb + (xarr[q] ? BL_OFF : BH_OFF) + SWZ(xt[q] * 128 + xg[q] * 16),
                     src + xt[q] * INF + k0 + xg[q] * 8);
            }
            cp_commit();
        }

        // ---- compute: 4 k16-steps, 2 n-groups, hi+lo into same fp32 acc ----
        const uint32_t sbh = bufb + BH_OFF;
        const uint32_t sbl = bufb + BL_OFF;
#pragma unroll
        for (int ks = 0; ks < 4; ks++) {
            uint32_t a[4], b[4];
            const int kb = ks * 32;

            ldsm_x4(bufb + SWZ(rowA * 128 + kb + aCsel), a[0], a[1], a[2], a[3]);

            const int bb = tokB * 128 + kb + bCsel;
            ldsm_x4(sbh + SWZ(bb), b[0], b[1], b[2], b[3]);
            mma_16816(acc[0], a, b + 0);
            mma_16816(acc[1], a, b + 2);
            ldsm_x4(sbl + SWZ(bb), b[0], b[1], b[2], b[3]);
            mma_16816(acc[0], a, b + 0);
            mma_16816(acc[1], a, b + 2);
        }
    }

    // ---- epilogue: atomicAdd partials (2 deterministic contributors/elem) ----
    const int g = lane >> 2;
    const int t2 = (lane & 3) * 2;
    const int f0 = row_base + rg * 16 + g;
#pragma unroll
    for (int nt = 0; nt < 2; nt++) {
        const int tok = th * 16 + nt * 8 + t2;
        atomicAdd(&out[(size_t)tok * OUTF + f0],           acc[nt][0]);
        atomicAdd(&out[(size_t)(tok + 1) * OUTF + f0],     acc[nt][1]);
        atomicAdd(&out[(size_t)tok * OUTF + f0 + 8],       acc[nt][2]);
        atomicAdd(&out[(size_t)(tok + 1) * OUTF + f0 + 8], acc[nt][3]);
    }
}

// ---------------- launch ----------------
extern "C" void kernel_launch(void* const* d_in, const int* in_sizes, int n_in,
                              void* d_out, int out_size) {
    const float* x      = (const float*)d_in[0];
    const int*   weight = (const int*)d_in[1];
    const float* scales = (const float*)d_in[2];
    float*       out    = (float*)d_out;
    (void)in_sizes; (void)n_in;

    cudaMemsetAsync(out, 0, (size_t)out_size * sizeof(float));
    prep_kernel<<<(TOKENS * INF + 255) / 256, 256>>>(x, scales);
    qgemm_kernel<<<(OUTF / TILE_M) * KSPLIT, 256>>>(weight, out);
}